// round 14
// baseline (speedup 1.0000x reference)
#include <cuda_runtime.h>
#include <cuda_bf16.h>
#include <cuda_fp16.h>
#include <cstdint>

#define P  4
#define NN 100000
#define MM 50000
#define EE 400000
#define DD 128

#define NCHUNK 49                         // ceil(MM/1024)
#define NPAIR  16

// ---------------- device scratch (no runtime allocation allowed) ------------
__device__ __align__(16) uint32_t g_yh[(size_t)P * NN * 64];   // 102.4 MB : fp16x2 y = x @ W_neigh
__device__ __align__(16) float g_self[P * MM * DD];            // 102.4 MB : x[:M] @ W_self + b
__device__ int   g_deg[NPAIR * MM];
__device__ int   g_off[NPAIR * MM];
__device__ int   g_cur[NPAIR * MM];
__device__ __align__(8) int2 g_hdr[NPAIR * MM];                // (off, deg) packed
__device__ int   g_csr[(size_t)NPAIR * EE];
__device__ int   g_bsum[NPAIR * NCHUNK];
__device__ int   g_boff[NPAIR * NCHUNK];
// W transposed to [n][k], split hi/lo bf16: per s, hi = 8192 u32, then lo
__device__ __align__(16) uint32_t g_wn[P * 16384];
__device__ __align__(16) uint32_t g_ws[P * 16384];

// off-diagonal pairs (pair = s*4 + d), ascending = s-major order
__constant__ int c_offd[12] = {1, 2, 3, 4, 6, 7, 8, 9, 11, 12, 13, 14};

// ============================================================================
// CSR build
// ============================================================================
__global__ void k_zero() {
    int i = blockIdx.x * blockDim.x + threadIdx.x;
    if (i < NPAIR * MM / 4) {
        ((int4*)g_deg)[i] = make_int4(0, 0, 0, 0);
        ((int4*)g_cur)[i] = make_int4(0, 0, 0, 0);
    }
}

__global__ void k_count(const int* __restrict__ edst) {
    int pair = blockIdx.y;
    int e4 = blockIdx.x * blockDim.x + threadIdx.x;
    if (e4 * 4 >= EE) return;
    int4 v = ((const int4*)(edst + (size_t)pair * EE))[e4];
    atomicAdd(&g_deg[pair * MM + v.x], 1);
    atomicAdd(&g_deg[pair * MM + v.y], 1);
    atomicAdd(&g_deg[pair * MM + v.z], 1);
    atomicAdd(&g_deg[pair * MM + v.w], 1);
}

__global__ __launch_bounds__(1024) void k_scan1() {
    int bx = blockIdx.x;
    int pair = bx / NCHUNK, chunk = bx % NCHUNK;
    int tid = threadIdx.x, lane = tid & 31, warp = tid >> 5;
    int idx = chunk * 1024 + tid;
    int v = (idx < MM) ? g_deg[pair * MM + idx] : 0;
    int x = v;
    #pragma unroll
    for (int o = 1; o < 32; o <<= 1) {
        int t = __shfl_up_sync(0xFFFFFFFF, x, o);
        if (lane >= o) x += t;
    }
    __shared__ int ws[32];
    if (lane == 31) ws[warp] = x;
    __syncthreads();
    if (warp == 0) {
        int y = ws[lane];
        #pragma unroll
        for (int o = 1; o < 32; o <<= 1) {
            int t = __shfl_up_sync(0xFFFFFFFF, y, o);
            if (lane >= o) y += t;
        }
        ws[lane] = y;
    }
    __syncthreads();
    int incl = x + (warp > 0 ? ws[warp - 1] : 0);
    if (idx < MM) g_off[pair * MM + idx] = incl - v;
    if (tid == 1023) g_bsum[bx] = incl;
}

__global__ __launch_bounds__(1024) void k_scan2() {
    __shared__ int sm[NPAIR * NCHUNK];
    int tid = threadIdx.x;
    for (int i = tid; i < NPAIR * NCHUNK; i += 1024) sm[i] = g_bsum[i];
    __syncthreads();
    if (tid < NPAIR) {
        int run = 0;
        for (int j = 0; j < NCHUNK; j++) {
            int t = sm[tid * NCHUNK + j];
            sm[tid * NCHUNK + j] = run;
            run += t;
        }
    }
    __syncthreads();
    for (int i = tid; i < NPAIR * NCHUNK; i += 1024) g_boff[i] = sm[i];
}

// scan3: finalize offsets AND pack (off, deg) header
__global__ __launch_bounds__(1024) void k_scan3() {
    int bx = blockIdx.x;
    int pair = bx / NCHUNK, chunk = bx % NCHUNK;
    int idx = chunk * 1024 + threadIdx.x;
    if (idx < MM) {
        int i = pair * MM + idx;
        int off = g_off[i] + g_boff[bx];
        g_off[i] = off;
        g_hdr[i] = make_int2(off, g_deg[i]);
    }
}

__global__ void k_fill(const int* __restrict__ esrc, const int* __restrict__ edst) {
    int pair = blockIdx.y;
    int e4 = blockIdx.x * blockDim.x + threadIdx.x;
    if (e4 * 4 >= EE) return;
    int4 s = ((const int4*)(esrc + (size_t)pair * EE))[e4];
    int4 d = ((const int4*)(edst + (size_t)pair * EE))[e4];
    int b = pair * MM;
    int* csr = g_csr + (size_t)pair * EE;
    int p0 = atomicAdd(&g_cur[b + d.x], 1); csr[g_off[b + d.x] + p0] = s.x;
    int p1 = atomicAdd(&g_cur[b + d.y], 1); csr[g_off[b + d.y] + p1] = s.y;
    int p2 = atomicAdd(&g_cur[b + d.z], 1); csr[g_off[b + d.z] + p2] = s.z;
    int p3 = atomicAdd(&g_cur[b + d.w], 1); csr[g_off[b + d.w] + p3] = s.w;
}

// ============================================================================
// W precompute: B[n][k] = W[k][n], split hi/lo bf16
// ============================================================================
__global__ __launch_bounds__(256) void k_prepw(const float* __restrict__ Wn,
                                               const float* __restrict__ Ws) {
    int s = blockIdx.x;
    const float* W = (blockIdx.y == 0) ? (Wn + s * DD * DD) : (Ws + s * DD * DD);
    uint32_t* dst = (blockIdx.y == 0) ? (g_wn + s * 16384) : (g_ws + s * 16384);
    for (int it = threadIdx.x; it < 128 * 64; it += 256) {
        int n = it >> 6;
        int k2 = it & 63;
        float f0 = W[(k2 * 2 + 0) * DD + n];
        float f1 = W[(k2 * 2 + 1) * DD + n];
        __nv_bfloat16 h0 = __float2bfloat16(f0), h1 = __float2bfloat16(f1);
        __nv_bfloat16 l0 = __float2bfloat16(f0 - __bfloat162float(h0));
        __nv_bfloat16 l1 = __float2bfloat16(f1 - __bfloat162float(h1));
        dst[n * 64 + k2] = ((uint32_t)__bfloat16_as_ushort(h1) << 16) | __bfloat16_as_ushort(h0);
        dst[8192 + n * 64 + k2] = ((uint32_t)__bfloat16_as_ushort(l1) << 16) | __bfloat16_as_ushort(l0);
    }
}

// ============================================================================
// mma.sync bf16 (hi/lo split, 3 passes)
// ============================================================================
__device__ __forceinline__ void mma16816(float* c, const uint32_t* a, const uint32_t* b) {
    asm volatile(
        "mma.sync.aligned.m16n8k16.row.col.f32.bf16.bf16.f32 "
        "{%0,%1,%2,%3}, {%4,%5,%6,%7}, {%8,%9}, {%0,%1,%2,%3};"
        : "+f"(c[0]), "+f"(c[1]), "+f"(c[2]), "+f"(c[3])
        : "r"(a[0]), "r"(a[1]), "r"(a[2]), "r"(a[3]), "r"(b[0]), "r"(b[1]));
}

#define PITCH   272
#define TILE_B  34816                     // one hi or lo tile at pitch 272

// Shared A-tile loader: loads 128 rows of x starting at row0, splits hi/lo,
// stores swizzle-free at pitch 272 into sm+SA_HI / sm+SA_LO.
__device__ __forceinline__ void load_a_split(char* sm, const float* A,
                                             int row0, int rows, int tid,
                                             int sa_hi, int sa_lo) {
    #pragma unroll
    for (int i = 0; i < 16; i++) {
        int idx = tid + i * 256;
        int r = idx >> 5, c4 = idx & 31;
        int gr = row0 + r;
        float4 v = make_float4(0.f, 0.f, 0.f, 0.f);
        if (gr < rows) v = *(const float4*)(A + (size_t)gr * DD + c4 * 4);
        __nv_bfloat16 h0 = __float2bfloat16(v.x), h1 = __float2bfloat16(v.y);
        __nv_bfloat16 h2 = __float2bfloat16(v.z), h3 = __float2bfloat16(v.w);
        __nv_bfloat16 l0 = __float2bfloat16(v.x - __bfloat162float(h0));
        __nv_bfloat16 l1 = __float2bfloat16(v.y - __bfloat162float(h1));
        __nv_bfloat16 l2 = __float2bfloat16(v.z - __bfloat162float(h2));
        __nv_bfloat16 l3 = __float2bfloat16(v.w - __bfloat162float(h3));
        uint2 hi = make_uint2(((uint32_t)__bfloat16_as_ushort(h1) << 16) | __bfloat16_as_ushort(h0),
                              ((uint32_t)__bfloat16_as_ushort(h3) << 16) | __bfloat16_as_ushort(h2));
        uint2 lo = make_uint2(((uint32_t)__bfloat16_as_ushort(l1) << 16) | __bfloat16_as_ushort(l0),
                              ((uint32_t)__bfloat16_as_ushort(l3) << 16) | __bfloat16_as_ushort(l2));
        *(uint2*)(sm + sa_hi + r * PITCH + c4 * 8) = hi;
        *(uint2*)(sm + sa_lo + r * PITCH + c4 * 8) = lo;
    }
}

__device__ __forceinline__ void load_b_split(char* sm, const uint32_t* Wsrc,
                                             int tid, int sb_hi, int sb_lo) {
    const uint2* srch = (const uint2*)(Wsrc);
    const uint2* srcl = (const uint2*)(Wsrc + 8192);
    #pragma unroll
    for (int i = 0; i < 16; i++) {
        int idx = tid + i * 256;
        int n = idx >> 5, k4 = idx & 31;
        *(uint2*)(sm + sb_hi + n * PITCH + k4 * 8) = srch[idx];
        *(uint2*)(sm + sb_lo + n * PITCH + k4 * 8) = srcl[idx];
    }
}

// ---------------- y-only GEMM (rows [row_base, row_base+grid*128) of x) -----
#define SA_HI   0
#define SA_LO   TILE_B
#define SB_HI   (2 * TILE_B)
#define SB_LO   (3 * TILE_B)
#define SM_TOT_Y (4 * TILE_B + 512)

__global__ __launch_bounds__(256, 1)
void k_gemm_y(const float* __restrict__ Aall, const uint32_t* __restrict__ Wall,
              uint32_t* __restrict__ Ch, int row_base)
{
    extern __shared__ char sm[];
    const int s = blockIdx.y;
    const int row0 = row_base + blockIdx.x * 128;
    const int tid = threadIdx.x;
    const int wid = tid >> 5, lane = tid & 31;

    load_b_split(sm, Wall + s * 16384, tid, SB_HI, SB_LO);
    load_a_split(sm, Aall + (size_t)s * NN * DD, row0, NN, tid, SA_HI, SA_LO);
    __syncthreads();

    const int wm = wid & 3;
    const int wn = wid >> 2;
    const int r_in = lane >> 2;
    const int cp = lane & 3;

    float c[2][8][4];
    #pragma unroll
    for (int mt = 0; mt < 2; mt++)
        #pragma unroll
        for (int nt = 0; nt < 8; nt++)
            #pragma unroll
            for (int j = 0; j < 4; j++) c[mt][nt][j] = 0.f;

    const int aoff[3] = {SA_HI, SA_HI, SA_LO};
    const int boff[3] = {SB_HI, SB_LO, SB_HI};
    #pragma unroll
    for (int pass = 0; pass < 3; pass++) {
        const char* Ab = sm + aoff[pass];
        const char* Bb = sm + boff[pass];
        #pragma unroll
        for (int kk = 0; kk < 8; kk++) {
            const int kb = kk * 32 + cp * 4;
            uint32_t af[2][4], bf[8][2];
            #pragma unroll
            for (int mt = 0; mt < 2; mt++) {
                const char* ap = Ab + (wm * 32 + mt * 16 + r_in) * PITCH + kb;
                af[mt][0] = *(const uint32_t*)(ap);
                af[mt][1] = *(const uint32_t*)(ap + 8 * PITCH);
                af[mt][2] = *(const uint32_t*)(ap + 16);
                af[mt][3] = *(const uint32_t*)(ap + 8 * PITCH + 16);
            }
            #pragma unroll
            for (int nt = 0; nt < 8; nt++) {
                const char* bp = Bb + (wn * 64 + nt * 8 + r_in) * PITCH + kb;
                bf[nt][0] = *(const uint32_t*)(bp);
                bf[nt][1] = *(const uint32_t*)(bp + 16);
            }
            #pragma unroll
            for (int mt = 0; mt < 2; mt++)
                #pragma unroll
                for (int nt = 0; nt < 8; nt++)
                    mma16816(c[mt][nt], af[mt], bf[nt]);
        }
    }

    #pragma unroll
    for (int mt = 0; mt < 2; mt++) {
        int gr0 = row0 + wm * 32 + mt * 16 + r_in;
        #pragma unroll
        for (int nt = 0; nt < 8; nt++) {
            int col = wn * 64 + nt * 8 + cp * 2;
            if (gr0 < NN) {
                __half2 h = __floats2half2_rn(c[mt][nt][0], c[mt][nt][1]);
                Ch[(size_t)(s * NN + gr0) * 64 + (col >> 1)] = *(uint32_t*)&h;
            }
            if (gr0 + 8 < NN) {
                __half2 h = __floats2half2_rn(c[mt][nt][2], c[mt][nt][3]);
                Ch[(size_t)(s * NN + gr0 + 8) * 64 + (col >> 1)] = *(uint32_t*)&h;
            }
        }
    }
}

// ---------------- fused GEMM for shared rows [0, MM): y AND self ------------
#define FB_N_HI (2 * TILE_B)
#define FB_N_LO (3 * TILE_B)
#define FB_S_HI (4 * TILE_B)
#define FB_S_LO (5 * TILE_B)
#define FM_BIAS (6 * TILE_B)
#define SM_TOT_F (6 * TILE_B + 512)

__global__ __launch_bounds__(256, 1)
void k_gemm_fused(const float* __restrict__ Aall, const uint32_t* __restrict__ Wn,
                  const uint32_t* __restrict__ Ws, const float* __restrict__ bias,
                  uint32_t* __restrict__ Ch, float* __restrict__ Cs)
{
    extern __shared__ char sm[];
    const int s = blockIdx.y;
    const int row0 = blockIdx.x * 128;
    const int tid = threadIdx.x;
    const int wid = tid >> 5, lane = tid & 31;

    float* bias_sm = (float*)(sm + FM_BIAS);
    if (tid < 128) bias_sm[tid] = bias[s * DD + tid];

    load_b_split(sm, Wn + s * 16384, tid, FB_N_HI, FB_N_LO);
    load_b_split(sm, Ws + s * 16384, tid, FB_S_HI, FB_S_LO);
    load_a_split(sm, Aall + (size_t)s * NN * DD, row0, MM, tid, SA_HI, SA_LO);
    __syncthreads();

    const int wm = wid & 3;
    const int wn = wid >> 2;
    const int r_in = lane >> 2;
    const int cp = lane & 3;

    float cy[2][8][4], cs[2][8][4];
    #pragma unroll
    for (int mt = 0; mt < 2; mt++)
        #pragma unroll
        for (int nt = 0; nt < 8; nt++)
            #pragma unroll
            for (int j = 0; j < 4; j++) { cy[mt][nt][j] = 0.f; cs[mt][nt][j] = 0.f; }

    const int aoff[3] = {SA_HI, SA_HI, SA_LO};
    const int bsel[3] = {0, 1, 0};      // 0 = hi B, 1 = lo B
    #pragma unroll
    for (int pass = 0; pass < 3; pass++) {
        const char* Ab = sm + aoff[pass];
        const char* Bn = sm + (bsel[pass] ? FB_N_LO : FB_N_HI);
        const char* Bs = sm + (bsel[pass] ? FB_S_LO : FB_S_HI);
        #pragma unroll
        for (int kk = 0; kk < 8; kk++) {
            const int kb = kk * 32 + cp * 4;
            uint32_t af[2][4];
            #pragma unroll
            for (int mt = 0; mt < 2; mt++) {
                const char* ap = Ab + (wm * 32 + mt * 16 + r_in) * PITCH + kb;
                af[mt][0] = *(const uint32_t*)(ap);
                af[mt][1] = *(const uint32_t*)(ap + 8 * PITCH);
                af[mt][2] = *(const uint32_t*)(ap + 16);
                af[mt][3] = *(const uint32_t*)(ap + 8 * PITCH + 16);
            }
            #pragma unroll
            for (int nt = 0; nt < 8; nt++) {
                const char* bp = Bn + (wn * 64 + nt * 8 + r_in) * PITCH + kb;
                uint32_t b0 = *(const uint32_t*)(bp);
                uint32_t b1 = *(const uint32_t*)(bp + 16);
                uint32_t bb[2] = {b0, b1};
                #pragma unroll
                for (int mt = 0; mt < 2; mt++) mma16816(cy[mt][nt], af[mt], bb);
            }
            #pragma unroll
            for (int nt = 0; nt < 8; nt++) {
                const char* bp = Bs + (wn * 64 + nt * 8 + r_in) * PITCH + kb;
                uint32_t b0 = *(const uint32_t*)(bp);
                uint32_t b1 = *(const uint32_t*)(bp + 16);
                uint32_t bb[2] = {b0, b1};
                #pragma unroll
                for (int mt = 0; mt < 2; mt++) mma16816(cs[mt][nt], af[mt], bb);
            }
        }
    }

    #pragma unroll
    for (int mt = 0; mt < 2; mt++) {
        int gr0 = row0 + wm * 32 + mt * 16 + r_in;
        #pragma unroll
        for (int nt = 0; nt < 8; nt++) {
            int col = wn * 64 + nt * 8 + cp * 2;
            float b0 = bias_sm[col], b1 = bias_sm[col + 1];
            if (gr0 < MM) {
                __half2 h = __floats2half2_rn(cy[mt][nt][0], cy[mt][nt][1]);
                Ch[(size_t)(s * NN + gr0) * 64 + (col >> 1)] = *(uint32_t*)&h;
                *(float2*)(Cs + ((size_t)s * MM + gr0) * DD + col) =
                    make_float2(cs[mt][nt][0] + b0, cs[mt][nt][1] + b1);
            }
            if (gr0 + 8 < MM) {
                __half2 h = __floats2half2_rn(cy[mt][nt][2], cy[mt][nt][3]);
                Ch[(size_t)(s * NN + gr0 + 8) * 64 + (col >> 1)] = *(uint32_t*)&h;
                *(float2*)(Cs + ((size_t)s * MM + gr0 + 8) * DD + col) =
                    make_float2(cs[mt][nt][2] + b0, cs[mt][nt][3] + b1);
            }
        }
    }
}

// ============================================================================
// Aggregation (R12 verbatim: one warp per row, simple loop — do not touch).
// ============================================================================
__device__ __forceinline__ float4 gather_h(const uint32_t* ys, int src, int lane) {
    uint2 v = *(const uint2*)(ys + (size_t)src * 64 + lane * 2);
    float2 f0 = __half22float2(*(__half2*)&v.x);
    float2 f1 = __half22float2(*(__half2*)&v.y);
    return make_float4(f0.x, f0.y, f1.x, f1.y);
}

#define BPP (MM / 8)   // 6250 blocks/pair, 8 warps/block

__global__ __launch_bounds__(256) void k_diag(float* __restrict__ out) {
    const int d = blockIdx.y;
    const int pair = d * 5;
    const int lane = threadIdx.x & 31;
    const int m = blockIdx.x * 8 + (threadIdx.x >> 5);
    const int mi = pair * MM + m;

    const int2 hdr = g_hdr[mi];              // (off, deg) in one 8B load
    const int cnt = hdr.y;
    const float inv = 1.0f / fmaxf((float)cnt, 1.0f);
    const int* cs = g_csr + (size_t)pair * EE + hdr.x;
    const uint32_t* ys = g_yh + (size_t)d * NN * 64;

    float4 acc = make_float4(0.f, 0.f, 0.f, 0.f);
    for (int e = 0; e < cnt; e++) {
        float4 v = gather_h(ys, cs[e], lane);
        acc.x += v.x; acc.y += v.y; acc.z += v.z; acc.w += v.w;
    }
    float4 sv = *(const float4*)&g_self[((size_t)d * MM + m) * DD + lane * 4];
    *(float4*)&out[((size_t)d * MM + m) * DD + lane * 4] =
        make_float4(sv.x + acc.x * inv, sv.y + acc.y * inv,
                    sv.z + acc.z * inv, sv.w + acc.w * inv);
}

__global__ __launch_bounds__(256) void k_offdiag(const int* __restrict__ merge,
                                                 float* __restrict__ out) {
    const int pair = c_offd[blockIdx.x / BPP];  // s-major ordering
    const int s = pair >> 2, d = pair & 3;
    const int lane = threadIdx.x & 31;
    const int m = (blockIdx.x % BPP) * 8 + (threadIdx.x >> 5);
    const int mi = pair * MM + m;

    const int2 hdr = g_hdr[mi];
    const int cnt = hdr.y;
    const float inv = 1.0f / fmaxf((float)cnt, 1.0f);
    const int* cs = g_csr + (size_t)pair * EE + hdr.x;
    const uint32_t* ys = g_yh + (size_t)s * NN * 64;

    float4 acc = make_float4(0.f, 0.f, 0.f, 0.f);
    for (int e = 0; e < cnt; e++) {
        float4 v = gather_h(ys, cs[e], lane);
        acc.x += v.x; acc.y += v.y; acc.z += v.z; acc.w += v.w;
    }
    float4 sv = *(const float4*)&g_self[((size_t)s * MM + m) * DD + lane * 4];
    int t = merge[(size_t)pair * MM + m];

    float* p = out + ((size_t)d * MM + t) * DD + lane * 4;
    atomicAdd(p + 0, sv.x + acc.x * inv);
    atomicAdd(p + 1, sv.y + acc.y * inv);
    atomicAdd(p + 2, sv.z + acc.z * inv);
    atomicAdd(p + 3, sv.w + acc.w * inv);
}

// ============================================================================
extern "C" void kernel_launch(void* const* d_in, const int* in_sizes, int n_in,
                              void* d_out, int out_size) {
    const float* x      = (const float*)d_in[0];
    const float* Wself  = (const float*)d_in[1];
    const float* Wneigh = (const float*)d_in[2];
    const float* bias   = (const float*)d_in[3];
    const int*   esrc   = (const int*)d_in[4];
    const int*   edst   = (const int*)d_in[5];
    const int*   merge  = (const int*)d_in[6];
    float*       out    = (float*)d_out;

    void *y_p, *self_p, *wn_p, *ws_p;
    cudaGetSymbolAddress(&y_p, g_yh);
    cudaGetSymbolAddress(&self_p, g_self);
    cudaGetSymbolAddress(&wn_p, g_wn);
    cudaGetSymbolAddress(&ws_p, g_ws);

    // One-time infra (created on the uncaptured correctness call).
    static cudaStream_t s2 = nullptr;
    static cudaEvent_t ev_fork = nullptr, ev_join = nullptr;
    if (!s2) {
        cudaStreamCreateWithFlags(&s2, cudaStreamNonBlocking);
        cudaEventCreateWithFlags(&ev_fork, cudaEventDisableTiming);
        cudaEventCreateWithFlags(&ev_join, cudaEventDisableTiming);
        cudaFuncSetAttribute(k_gemm_y, cudaFuncAttributeMaxDynamicSharedMemorySize, SM_TOT_Y);
        cudaFuncSetAttribute(k_gemm_fused, cudaFuncAttributeMaxDynamicSharedMemorySize, SM_TOT_F);
    }

    // ---- fork: CSR build on s2, GEMM chain on the main stream --------------
    cudaEventRecord(ev_fork, 0);
    cudaStreamWaitEvent(s2, ev_fork, 0);

    // side stream: CSR build (int-atomic / L2-bound)
    k_zero<<<(NPAIR * MM / 4 + 255) / 256, 256, 0, s2>>>();
    k_count<<<dim3((EE / 4 + 255) / 256, NPAIR), 256, 0, s2>>>(edst);
    k_scan1<<<NPAIR * NCHUNK, 1024, 0, s2>>>();
    k_scan2<<<1, 1024, 0, s2>>>();
    k_scan3<<<NPAIR * NCHUNK, 1024, 0, s2>>>();
    k_fill<<<dim3((EE / 4 + 255) / 256, NPAIR), 256, 0, s2>>>(esrc, edst);
    cudaEventRecord(ev_join, s2);

    // main stream: W precompute + tensor-core GEMMs
    //   fused: rows [0,50k) -> y (fp16) AND self (fp32+bias), x read ONCE
    //   y-hi:  rows [50k,100k) -> y only
    k_prepw<<<dim3(P, 2), 256>>>(Wneigh, Wself);
    k_gemm_fused<<<dim3((MM + 127) / 128, P), 256, SM_TOT_F>>>(
        x, (const uint32_t*)wn_p, (const uint32_t*)ws_p, bias,
        (uint32_t*)y_p, (float*)self_p);
    k_gemm_y<<<dim3((NN - MM + 127) / 128, P), 256, SM_TOT_Y>>>(
        x, (const uint32_t*)wn_p, (uint32_t*)y_p, MM);

    // ---- join, then aggregation --------------------------------------------
    cudaStreamWaitEvent(0, ev_join, 0);
    k_diag<<<dim3(BPP, P), 256>>>(out);
    k_offdiag<<<12 * BPP, 256>>>(merge, out);
}

// round 15
// speedup vs baseline: 1.1027x; 1.1027x over previous
#include <cuda_runtime.h>
#include <cuda_bf16.h>
#include <cuda_fp16.h>
#include <cstdint>

#define P  4
#define NN 100000
#define MM 50000
#define EE 400000
#define DD 128

#define NCHUNK 49                         // ceil(MM/1024)
#define NPAIR  16

// ---------------- device scratch (no runtime allocation allowed) ------------
__device__ __align__(16) uint32_t g_yh[(size_t)P * NN * 64];   // 102.4 MB : fp16x2 y = x @ W_neigh
__device__ __align__(16) float g_self[P * MM * DD];            // 102.4 MB : x[:M] @ W_self + b
__device__ int   g_deg[NPAIR * MM];
__device__ int   g_off[NPAIR * MM];
__device__ int   g_cur[NPAIR * MM];
__device__ __align__(8) int2 g_hdr[NPAIR * MM];                // (off, deg) packed
__device__ int   g_csr[(size_t)NPAIR * EE];
__device__ int   g_bsum[NPAIR * NCHUNK];
__device__ int   g_boff[NPAIR * NCHUNK];
// W transposed to [n][k], split hi/lo bf16: per s, hi = 8192 u32, then lo
__device__ __align__(16) uint32_t g_wn[P * 16384];
__device__ __align__(16) uint32_t g_ws[P * 16384];

// off-diagonal pairs (pair = s*4 + d), ascending = s-major order
__constant__ int c_offd[12] = {1, 2, 3, 4, 6, 7, 8, 9, 11, 12, 13, 14};

// ============================================================================
// CSR build
// ============================================================================
__global__ void k_zero() {
    int i = blockIdx.x * blockDim.x + threadIdx.x;
    if (i < NPAIR * MM / 4) {
        ((int4*)g_deg)[i] = make_int4(0, 0, 0, 0);
        ((int4*)g_cur)[i] = make_int4(0, 0, 0, 0);
    }
}

__global__ void k_count(const int* __restrict__ edst) {
    int pair = blockIdx.y;
    int e4 = blockIdx.x * blockDim.x + threadIdx.x;
    if (e4 * 4 >= EE) return;
    int4 v = ((const int4*)(edst + (size_t)pair * EE))[e4];
    atomicAdd(&g_deg[pair * MM + v.x], 1);
    atomicAdd(&g_deg[pair * MM + v.y], 1);
    atomicAdd(&g_deg[pair * MM + v.z], 1);
    atomicAdd(&g_deg[pair * MM + v.w], 1);
}

__global__ __launch_bounds__(1024) void k_scan1() {
    int bx = blockIdx.x;
    int pair = bx / NCHUNK, chunk = bx % NCHUNK;
    int tid = threadIdx.x, lane = tid & 31, warp = tid >> 5;
    int idx = chunk * 1024 + tid;
    int v = (idx < MM) ? g_deg[pair * MM + idx] : 0;
    int x = v;
    #pragma unroll
    for (int o = 1; o < 32; o <<= 1) {
        int t = __shfl_up_sync(0xFFFFFFFF, x, o);
        if (lane >= o) x += t;
    }
    __shared__ int ws[32];
    if (lane == 31) ws[warp] = x;
    __syncthreads();
    if (warp == 0) {
        int y = ws[lane];
        #pragma unroll
        for (int o = 1; o < 32; o <<= 1) {
            int t = __shfl_up_sync(0xFFFFFFFF, y, o);
            if (lane >= o) y += t;
        }
        ws[lane] = y;
    }
    __syncthreads();
    int incl = x + (warp > 0 ? ws[warp - 1] : 0);
    if (idx < MM) g_off[pair * MM + idx] = incl - v;
    if (tid == 1023) g_bsum[bx] = incl;
}

__global__ __launch_bounds__(1024) void k_scan2() {
    __shared__ int sm[NPAIR * NCHUNK];
    int tid = threadIdx.x;
    for (int i = tid; i < NPAIR * NCHUNK; i += 1024) sm[i] = g_bsum[i];
    __syncthreads();
    if (tid < NPAIR) {
        int run = 0;
        for (int j = 0; j < NCHUNK; j++) {
            int t = sm[tid * NCHUNK + j];
            sm[tid * NCHUNK + j] = run;
            run += t;
        }
    }
    __syncthreads();
    for (int i = tid; i < NPAIR * NCHUNK; i += 1024) g_boff[i] = sm[i];
}

// scan3: finalize offsets AND pack (off, deg) header
__global__ __launch_bounds__(1024) void k_scan3() {
    int bx = blockIdx.x;
    int pair = bx / NCHUNK, chunk = bx % NCHUNK;
    int idx = chunk * 1024 + threadIdx.x;
    if (idx < MM) {
        int i = pair * MM + idx;
        int off = g_off[i] + g_boff[bx];
        g_off[i] = off;
        g_hdr[i] = make_int2(off, g_deg[i]);
    }
}

__global__ void k_fill(const int* __restrict__ esrc, const int* __restrict__ edst) {
    int pair = blockIdx.y;
    int e4 = blockIdx.x * blockDim.x + threadIdx.x;
    if (e4 * 4 >= EE) return;
    int4 s = ((const int4*)(esrc + (size_t)pair * EE))[e4];
    int4 d = ((const int4*)(edst + (size_t)pair * EE))[e4];
    int b = pair * MM;
    int* csr = g_csr + (size_t)pair * EE;
    int p0 = atomicAdd(&g_cur[b + d.x], 1); csr[g_off[b + d.x] + p0] = s.x;
    int p1 = atomicAdd(&g_cur[b + d.y], 1); csr[g_off[b + d.y] + p1] = s.y;
    int p2 = atomicAdd(&g_cur[b + d.z], 1); csr[g_off[b + d.z] + p2] = s.z;
    int p3 = atomicAdd(&g_cur[b + d.w], 1); csr[g_off[b + d.w] + p3] = s.w;
}

// ============================================================================
// W precompute: B[n][k] = W[k][n], split hi/lo bf16
// ============================================================================
__global__ __launch_bounds__(256) void k_prepw(const float* __restrict__ Wn,
                                               const float* __restrict__ Ws) {
    int s = blockIdx.x;
    const float* W = (blockIdx.y == 0) ? (Wn + s * DD * DD) : (Ws + s * DD * DD);
    uint32_t* dst = (blockIdx.y == 0) ? (g_wn + s * 16384) : (g_ws + s * 16384);
    for (int it = threadIdx.x; it < 128 * 64; it += 256) {
        int n = it >> 6;
        int k2 = it & 63;
        float f0 = W[(k2 * 2 + 0) * DD + n];
        float f1 = W[(k2 * 2 + 1) * DD + n];
        __nv_bfloat16 h0 = __float2bfloat16(f0), h1 = __float2bfloat16(f1);
        __nv_bfloat16 l0 = __float2bfloat16(f0 - __bfloat162float(h0));
        __nv_bfloat16 l1 = __float2bfloat16(f1 - __bfloat162float(h1));
        dst[n * 64 + k2] = ((uint32_t)__bfloat16_as_ushort(h1) << 16) | __bfloat16_as_ushort(h0);
        dst[8192 + n * 64 + k2] = ((uint32_t)__bfloat16_as_ushort(l1) << 16) | __bfloat16_as_ushort(l0);
    }
}

// ============================================================================
// mma.sync bf16 GEMM (hi/lo split, 3 passes): C = A @ W (+bias)
// ============================================================================
__device__ __forceinline__ void mma16816(float* c, const uint32_t* a, const uint32_t* b) {
    asm volatile(
        "mma.sync.aligned.m16n8k16.row.col.f32.bf16.bf16.f32 "
        "{%0,%1,%2,%3}, {%4,%5,%6,%7}, {%8,%9}, {%0,%1,%2,%3};"
        : "+f"(c[0]), "+f"(c[1]), "+f"(c[2]), "+f"(c[3])
        : "r"(a[0]), "r"(a[1]), "r"(a[2]), "r"(a[3]), "r"(b[0]), "r"(b[1]));
}

#define PITCH   272
#define SA_HI   0
#define SA_LO   34816
#define SB_HI   69632
#define SB_LO   104448
#define SM_BIAS 139264
#define SM_TOT  (139264 + 512)

__global__ __launch_bounds__(256, 1)
void k_gemm(const float* __restrict__ Aall, const uint32_t* __restrict__ Wall,
            const float* __restrict__ bias, float* __restrict__ Cf,
            uint32_t* __restrict__ Ch, int rows, int strideA, int strideC)
{
    extern __shared__ char sm[];
    const int s = blockIdx.y;
    const int row0 = blockIdx.x * 128;
    const int tid = threadIdx.x;
    const int wid = tid >> 5, lane = tid & 31;

    float* bias_sm = (float*)(sm + SM_BIAS);
    if (tid < 128) bias_sm[tid] = bias ? bias[s * DD + tid] : 0.0f;

    {
        const uint2* srch = (const uint2*)(Wall + s * 16384);
        const uint2* srcl = (const uint2*)(Wall + s * 16384 + 8192);
        #pragma unroll
        for (int i = 0; i < 16; i++) {
            int idx = tid + i * 256;
            int n = idx >> 5, k4 = idx & 31;
            *(uint2*)(sm + SB_HI + n * PITCH + k4 * 8) = srch[idx];
            *(uint2*)(sm + SB_LO + n * PITCH + k4 * 8) = srcl[idx];
        }
    }
    {
        const float* A = Aall + (size_t)s * strideA;
        #pragma unroll
        for (int i = 0; i < 16; i++) {
            int idx = tid + i * 256;
            int r = idx >> 5, c4 = idx & 31;
            int gr = row0 + r;
            float4 v = make_float4(0.f, 0.f, 0.f, 0.f);
            if (gr < rows) v = *(const float4*)(A + (size_t)gr * DD + c4 * 4);
            __nv_bfloat16 h0 = __float2bfloat16(v.x), h1 = __float2bfloat16(v.y);
            __nv_bfloat16 h2 = __float2bfloat16(v.z), h3 = __float2bfloat16(v.w);
            __nv_bfloat16 l0 = __float2bfloat16(v.x - __bfloat162float(h0));
            __nv_bfloat16 l1 = __float2bfloat16(v.y - __bfloat162float(h1));
            __nv_bfloat16 l2 = __float2bfloat16(v.z - __bfloat162float(h2));
            __nv_bfloat16 l3 = __float2bfloat16(v.w - __bfloat162float(h3));
            uint2 hi = make_uint2(((uint32_t)__bfloat16_as_ushort(h1) << 16) | __bfloat16_as_ushort(h0),
                                  ((uint32_t)__bfloat16_as_ushort(h3) << 16) | __bfloat16_as_ushort(h2));
            uint2 lo = make_uint2(((uint32_t)__bfloat16_as_ushort(l1) << 16) | __bfloat16_as_ushort(l0),
                                  ((uint32_t)__bfloat16_as_ushort(l3) << 16) | __bfloat16_as_ushort(l2));
            *(uint2*)(sm + SA_HI + r * PITCH + c4 * 8) = hi;
            *(uint2*)(sm + SA_LO + r * PITCH + c4 * 8) = lo;
        }
    }
    __syncthreads();

    const int wm = wid & 3;
    const int wn = wid >> 2;
    const int r_in = lane >> 2;
    const int cp = lane & 3;

    float c[2][8][4];
    #pragma unroll
    for (int mt = 0; mt < 2; mt++)
        #pragma unroll
        for (int nt = 0; nt < 8; nt++)
            #pragma unroll
            for (int j = 0; j < 4; j++) c[mt][nt][j] = 0.f;

    const int aoff[3] = {SA_HI, SA_HI, SA_LO};
    const int boff[3] = {SB_HI, SB_LO, SB_HI};
    #pragma unroll
    for (int pass = 0; pass < 3; pass++) {
        const char* Ab = sm + aoff[pass];
        const char* Bb = sm + boff[pass];
        #pragma unroll
        for (int kk = 0; kk < 8; kk++) {
            const int kb = kk * 32 + cp * 4;
            uint32_t af[2][4], bf[8][2];
            #pragma unroll
            for (int mt = 0; mt < 2; mt++) {
                const char* ap = Ab + (wm * 32 + mt * 16 + r_in) * PITCH + kb;
                af[mt][0] = *(const uint32_t*)(ap);
                af[mt][1] = *(const uint32_t*)(ap + 8 * PITCH);
                af[mt][2] = *(const uint32_t*)(ap + 16);
                af[mt][3] = *(const uint32_t*)(ap + 8 * PITCH + 16);
            }
            #pragma unroll
            for (int nt = 0; nt < 8; nt++) {
                const char* bp = Bb + (wn * 64 + nt * 8 + r_in) * PITCH + kb;
                bf[nt][0] = *(const uint32_t*)(bp);
                bf[nt][1] = *(const uint32_t*)(bp + 16);
            }
            #pragma unroll
            for (int mt = 0; mt < 2; mt++)
                #pragma unroll
                for (int nt = 0; nt < 8; nt++)
                    mma16816(c[mt][nt], af[mt], bf[nt]);
        }
    }

    if (Ch) {    // fp16x2 output (y path, no bias)
        #pragma unroll
        for (int mt = 0; mt < 2; mt++) {
            int gr0 = row0 + wm * 32 + mt * 16 + r_in;
            #pragma unroll
            for (int nt = 0; nt < 8; nt++) {
                int col = wn * 64 + nt * 8 + cp * 2;
                if (gr0 < rows) {
                    __half2 h = __floats2half2_rn(c[mt][nt][0], c[mt][nt][1]);
                    Ch[(size_t)(s * NN + gr0) * 64 + (col >> 1)] = *(uint32_t*)&h;
                }
                if (gr0 + 8 < rows) {
                    __half2 h = __floats2half2_rn(c[mt][nt][2], c[mt][nt][3]);
                    Ch[(size_t)(s * NN + gr0 + 8) * 64 + (col >> 1)] = *(uint32_t*)&h;
                }
            }
        }
    } else {     // fp32 output (+bias)
        float* C = Cf + (size_t)s * strideC;
        #pragma unroll
        for (int mt = 0; mt < 2; mt++) {
            int gr0 = row0 + wm * 32 + mt * 16 + r_in;
            #pragma unroll
            for (int nt = 0; nt < 8; nt++) {
                int col = wn * 64 + nt * 8 + cp * 2;
                float b0 = bias_sm[col], b1 = bias_sm[col + 1];
                if (gr0 < rows)
                    *(float2*)(C + (size_t)gr0 * DD + col) =
                        make_float2(c[mt][nt][0] + b0, c[mt][nt][1] + b1);
                if (gr0 + 8 < rows)
                    *(float2*)(C + (size_t)(gr0 + 8) * DD + col) =
                        make_float2(c[mt][nt][2] + b0, c[mt][nt][3] + b1);
            }
        }
    }
}

// ============================================================================
// Aggregation (R12 verbatim — verified optimum; do not touch).
// ============================================================================
__device__ __forceinline__ float4 gather_h(const uint32_t* ys, int src, int lane) {
    uint2 v = *(const uint2*)(ys + (size_t)src * 64 + lane * 2);
    float2 f0 = __half22float2(*(__half2*)&v.x);
    float2 f1 = __half22float2(*(__half2*)&v.y);
    return make_float4(f0.x, f0.y, f1.x, f1.y);
}

#define BPP (MM / 8)   // 6250 blocks/pair, 8 warps/block

__global__ __launch_bounds__(256) void k_diag(float* __restrict__ out) {
    const int d = blockIdx.y;
    const int pair = d * 5;
    const int lane = threadIdx.x & 31;
    const int m = blockIdx.x * 8 + (threadIdx.x >> 5);
    const int mi = pair * MM + m;

    const int2 hdr = g_hdr[mi];              // (off, deg) in one 8B load
    const int cnt = hdr.y;
    const float inv = 1.0f / fmaxf((float)cnt, 1.0f);
    const int* cs = g_csr + (size_t)pair * EE + hdr.x;
    const uint32_t* ys = g_yh + (size_t)d * NN * 64;

    float4 acc = make_float4(0.f, 0.f, 0.f, 0.f);
    for (int e = 0; e < cnt; e++) {
        float4 v = gather_h(ys, cs[e], lane);
        acc.x += v.x; acc.y += v.y; acc.z += v.z; acc.w += v.w;
    }
    float4 sv = *(const float4*)&g_self[((size_t)d * MM + m) * DD + lane * 4];
    *(float4*)&out[((size_t)d * MM + m) * DD + lane * 4] =
        make_float4(sv.x + acc.x * inv, sv.y + acc.y * inv,
                    sv.z + acc.z * inv, sv.w + acc.w * inv);
}

__global__ __launch_bounds__(256) void k_offdiag(const int* __restrict__ merge,
                                                 float* __restrict__ out) {
    const int pair = c_offd[blockIdx.x / BPP];  // s-major ordering
    const int s = pair >> 2, d = pair & 3;
    const int lane = threadIdx.x & 31;
    const int m = (blockIdx.x % BPP) * 8 + (threadIdx.x >> 5);
    const int mi = pair * MM + m;

    const int2 hdr = g_hdr[mi];
    const int cnt = hdr.y;
    const float inv = 1.0f / fmaxf((float)cnt, 1.0f);
    const int* cs = g_csr + (size_t)pair * EE + hdr.x;
    const uint32_t* ys = g_yh + (size_t)s * NN * 64;

    float4 acc = make_float4(0.f, 0.f, 0.f, 0.f);
    for (int e = 0; e < cnt; e++) {
        float4 v = gather_h(ys, cs[e], lane);
        acc.x += v.x; acc.y += v.y; acc.z += v.z; acc.w += v.w;
    }
    float4 sv = *(const float4*)&g_self[((size_t)s * MM + m) * DD + lane * 4];
    int t = merge[(size_t)pair * MM + m];

    float* p = out + ((size_t)d * MM + t) * DD + lane * 4;
    atomicAdd(p + 0, sv.x + acc.x * inv);
    atomicAdd(p + 1, sv.y + acc.y * inv);
    atomicAdd(p + 2, sv.z + acc.z * inv);
    atomicAdd(p + 3, sv.w + acc.w * inv);
}

// ============================================================================
extern "C" void kernel_launch(void* const* d_in, const int* in_sizes, int n_in,
                              void* d_out, int out_size) {
    const float* x      = (const float*)d_in[0];
    const float* Wself  = (const float*)d_in[1];
    const float* Wneigh = (const float*)d_in[2];
    const float* bias   = (const float*)d_in[3];
    const int*   esrc   = (const int*)d_in[4];
    const int*   edst   = (const int*)d_in[5];
    const int*   merge  = (const int*)d_in[6];
    float*       out    = (float*)d_out;

    void *y_p, *self_p, *wn_p, *ws_p;
    cudaGetSymbolAddress(&y_p, g_yh);
    cudaGetSymbolAddress(&self_p, g_self);
    cudaGetSymbolAddress(&wn_p, g_wn);
    cudaGetSymbolAddress(&ws_p, g_ws);

    // One-time infra (created on the uncaptured correctness call).
    static cudaStream_t s2 = nullptr, s3 = nullptr;
    static cudaEvent_t ev_fork = nullptr, ev_join = nullptr;
    static cudaEvent_t ev_prepw = nullptr, ev_self = nullptr;
    if (!s2) {
        cudaStreamCreateWithFlags(&s2, cudaStreamNonBlocking);
        cudaStreamCreateWithFlags(&s3, cudaStreamNonBlocking);
        cudaEventCreateWithFlags(&ev_fork, cudaEventDisableTiming);
        cudaEventCreateWithFlags(&ev_join, cudaEventDisableTiming);
        cudaEventCreateWithFlags(&ev_prepw, cudaEventDisableTiming);
        cudaEventCreateWithFlags(&ev_self, cudaEventDisableTiming);
        cudaFuncSetAttribute(k_gemm, cudaFuncAttributeMaxDynamicSharedMemorySize, SM_TOT);
    }

    // ---- fork: CSR build on s2, GEMM chain on main + s3 ---------------------
    cudaEventRecord(ev_fork, 0);
    cudaStreamWaitEvent(s2, ev_fork, 0);

    // side stream s2: CSR build (int-atomic / L2-bound)
    k_zero<<<(NPAIR * MM / 4 + 255) / 256, 256, 0, s2>>>();
    k_count<<<dim3((EE / 4 + 255) / 256, NPAIR), 256, 0, s2>>>(edst);
    k_scan1<<<NPAIR * NCHUNK, 1024, 0, s2>>>();
    k_scan2<<<1, 1024, 0, s2>>>();
    k_scan3<<<NPAIR * NCHUNK, 1024, 0, s2>>>();
    k_fill<<<dim3((EE / 4 + 255) / 256, NPAIR), 256, 0, s2>>>(esrc, edst);
    cudaEventRecord(ev_join, s2);

    // main stream: W precompute, then y-GEMM; self-GEMM concurrently on s3
    k_prepw<<<dim3(P, 2), 256>>>(Wneigh, Wself);
    cudaEventRecord(ev_prepw, 0);
    cudaStreamWaitEvent(s3, ev_prepw, 0);

    k_gemm<<<dim3((NN + 127) / 128, P), 256, SM_TOT>>>(
        x, (const uint32_t*)wn_p, nullptr, nullptr, (uint32_t*)y_p, NN, NN * DD, 0);
    k_gemm<<<dim3((MM + 127) / 128, P), 256, SM_TOT, s3>>>(
        x, (const uint32_t*)ws_p, bias, (float*)self_p, nullptr, MM, NN * DD, MM * DD);
    cudaEventRecord(ev_self, s3);

    // ---- join, then aggregation --------------------------------------------
    cudaStreamWaitEvent(0, ev_join, 0);
    cudaStreamWaitEvent(0, ev_self, 0);
    k_diag<<<dim3(BPP, P), 256>>>(out);
    k_offdiag<<<12 * BPP, 256>>>(merge, out);
}